// round 4
// baseline (speedup 1.0000x reference)
#include <cuda_runtime.h>
#include <cuda_bf16.h>

#define BB 512
#define TT 512
#define LL 128
#define PADL 0
#define BOSL 1
#define EOSL 2

typedef unsigned long long ull;

// per-batch (logZ - gold); reduced by second kernel
__device__ float g_res[BB];

#define FMA2(d, a, b, c) \
    asm("fma.rn.f32x2 %0, %1, %2, %3;" : "=l"(d) : "l"(a), "l"(b), "l"(c))
#define ADD2(d, a, b) \
    asm("add.rn.f32x2 %0, %1, %2;" : "=l"(d) : "l"(a), "l"(b))

__device__ __forceinline__ ull pack2(float lo, float hi) {
    ull r;
    asm("mov.b64 %0, {%1, %2};" : "=l"(r) : "f"(lo), "f"(hi));
    return r;
}
__device__ __forceinline__ void unpack2(float& lo, float& hi, ull v) {
    asm("mov.b64 {%0, %1}, %2;" : "=f"(lo), "=f"(hi) : "l"(v));
}

__global__ __launch_bounds__(128, 3) void crf_fwd(
    const float* __restrict__ feat,   // [B, T, L] f32
    const int* __restrict__ tags,     // [B, T] i32
    const int* __restrict__ mask,     // [B, T] i32 (bool widened)
    const float* __restrict__ tr)     // [L, L] f32
{
    const int j    = threadIdx.x;   // label column 0..127
    const int b    = blockIdx.x;    // one batch per CTA
    const int lane = j & 31;
    const int wid  = j >> 5;

    __shared__ __align__(16) float u_sh[2][LL];  // [buf][i]
    __shared__ float c_sh[2];
    __shared__ int   s_len;
    __shared__ float s_red[4];
    __shared__ float s_gold;

    // ---- E column j packed in registers: E2[m] = (exp(tr[2m][j]), exp(tr[2m+1][j]))
    ull E2[64];
#pragma unroll
    for (int m = 0; m < 64; m++) {
        float lo = __expf(tr[(2 * m)     * LL + j]);
        float hi = __expf(tr[(2 * m + 1) * LL + j]);
        E2[m] = pack2(lo, hi);
    }

    // ---- sequence length (mask is a monotone prefix)
    if (j == 0) s_len = 0;
    __syncthreads();
    {
        int cnt = 0;
#pragma unroll
        for (int t = j; t < TT; t += 128) cnt += (mask[b * TT + t] != 0) ? 1 : 0;
#pragma unroll
        for (int o = 16; o > 0; o >>= 1) cnt += __shfl_down_sync(0xffffffffu, cnt, o);
        if (lane == 0) atomicAdd(&s_len, cnt);
    }
    __syncthreads();
    const int len = s_len;

    // ---- gold path score (all 128 threads cooperate)
    {
        float gp = 0.0f;
        for (int t = j; t < len; t += 128) {
            int tg   = tags[b * TT + t];
            float e  = feat[(b * TT + t) * LL + tg];
            int prev = (t == 0) ? BOSL : tags[b * TT + t - 1];
            gp += e + tr[prev * LL + tg];
        }
#pragma unroll
        for (int o = 16; o > 0; o >>= 1) gp += __shfl_down_sync(0xffffffffu, gp, o);
        if (lane == 0) s_red[wid] = gp;
    }
    __syncthreads();
    if (j == 0) {
        float g = s_red[0] + s_red[1] + s_red[2] + s_red[3];
        g += tr[tags[b * TT + len - 1] * LL + EOSL];
        s_gold = g;
    }

    // ---- forward recursion init: fv = tr[BOS,:] + feat[:,0,:]
    float fv = tr[BOSL * LL + j] + feat[(b * TT) * LL + j];
    if (j == 64) c_sh[0] = fv;
    __syncthreads();
    float c = c_sh[0];

    float ft = feat[(b * TT + 1) * LL + j];  // len >= 2 always (len in [256,512])

    int p = 0;
    for (int t = 1; t < len; t++) {
        // phase A: publish u = exp(fv - c) and next normalizer (fv[64])
        float u = __expf(fv - c);
        u_sh[p][j] = u;
        if (j == 64) c_sh[p] = fv;
        __syncthreads();
        float nc = c_sh[p];

        // prefetch next step's emission
        float nft = ft;
        if (t + 1 < len) nft = feat[(b * TT + t + 1) * LL + j];

        // phase B: v[j] = sum_i u[i] * E[i][j]   (E packed in regs, u via LDS.128 broadcast)
        const ulonglong2* U = (const ulonglong2*)(u_sh[p]);
        ull a0 = 0, a1 = 0, a2 = 0, a3 = 0;   // packed (0.0f, 0.0f)
#pragma unroll
        for (int q = 0; q < 16; q++) {
            ulonglong2 ua = U[2 * q];
            ulonglong2 ub = U[2 * q + 1];
            FMA2(a0, ua.x, E2[4 * q],     a0);
            FMA2(a1, ua.y, E2[4 * q + 1], a1);
            FMA2(a2, ub.x, E2[4 * q + 2], a2);
            FMA2(a3, ub.y, E2[4 * q + 3], a3);
        }
        ADD2(a0, a0, a2);
        ADD2(a1, a1, a3);
        ADD2(a0, a0, a1);
        float slo, shi;
        unpack2(slo, shi, a0);
        float s = slo + shi;

        fv = ft + c + __logf(s);
        c = nc;
        ft = nft;
        p ^= 1;
    }

    // ---- logZ = logsumexp_j(fv[j] + tr[j][EOS]); result = logZ - gold
    {
        float e = __expf((fv + tr[j * LL + EOSL]) - c);
#pragma unroll
        for (int o = 16; o > 0; o >>= 1) e += __shfl_down_sync(0xffffffffu, e, o);
        __syncthreads();
        if (lane == 0) s_red[wid] = e;
        __syncthreads();
        if (j == 0) {
            float z = s_red[0] + s_red[1] + s_red[2] + s_red[3];
            g_res[b] = (c + __logf(z)) - s_gold;
        }
    }
}

// deterministic fixed-order mean over the 512 per-batch results
__global__ void crf_reduce(float* __restrict__ out) {
    __shared__ float s[BB];
    int t = threadIdx.x;
    s[t] = g_res[t];
    __syncthreads();
#pragma unroll
    for (int k = BB / 2; k > 0; k >>= 1) {
        if (t < k) s[t] += s[t + k];
        __syncthreads();
    }
    if (t == 0) out[0] = s[0] * (1.0f / (float)BB);
}

extern "C" void kernel_launch(void* const* d_in, const int* in_sizes, int n_in,
                              void* d_out, int out_size) {
    const float* feat = (const float*)d_in[0];
    const int*   tags = (const int*)d_in[1];
    const int*   mask = (const int*)d_in[2];
    const float* tr   = (const float*)d_in[3];

    crf_fwd<<<BB, 128>>>(feat, tags, mask, tr);
    crf_reduce<<<1, BB>>>((float*)d_out);
}

// round 8
// speedup vs baseline: 1.3932x; 1.3932x over previous
#include <cuda_runtime.h>
#include <cuda_bf16.h>

#define BB 512
#define TT 512
#define LL 128
#define PADL 0
#define BOSL 1
#define EOSL 2

typedef unsigned long long ull;

// per-batch (logZ - gold); reduced by second kernel
__device__ float g_res[BB];

#define FMA2(d, a, b, c) \
    asm("fma.rn.f32x2 %0, %1, %2, %3;" : "=l"(d) : "l"(a), "l"(b), "l"(c))
#define ADD2(d, a, b) \
    asm("add.rn.f32x2 %0, %1, %2;" : "=l"(d) : "l"(a), "l"(b))

__device__ __forceinline__ ull pack2(float lo, float hi) {
    ull r;
    asm("mov.b64 %0, {%1, %2};" : "=l"(r) : "f"(lo), "f"(hi));
    return r;
}
__device__ __forceinline__ void unpack2(float& lo, float& hi, ull v) {
    asm("mov.b64 {%0, %1}, %2;" : "=f"(lo), "=f"(hi) : "l"(v));
}

__global__ __launch_bounds__(128, 2) void crf_fwd(
    const float* __restrict__ feat,   // [B, T, L] f32
    const int* __restrict__ tags,     // [B, T] i32
    const int* __restrict__ mask,     // [B, T] i32 (bool widened)
    const float* __restrict__ tr)     // [L, L] f32
{
    const int j    = threadIdx.x;   // label column 0..127
    const int b0   = blockIdx.x * 2;
    const int b1   = b0 + 1;
    const int lane = j & 31;
    const int wid  = j >> 5;

    __shared__ __align__(16) float u_sh[2][2][LL];  // [buf][batch][i]
    __shared__ float c_sh[2][2];
    __shared__ int   s_len[2];
    __shared__ float s_red[2][4];
    __shared__ float s_gold[2];

    // ---- E column j packed: E2[m] = (exp(tr[2m][j]), exp(tr[2m+1][j]))
    ull E2[64];
#pragma unroll
    for (int m = 0; m < 64; m++) {
        float lo = __expf(tr[(2 * m)     * LL + j]);
        float hi = __expf(tr[(2 * m + 1) * LL + j]);
        E2[m] = pack2(lo, hi);
    }

    // ---- sequence lengths (mask is a monotone prefix)
    if (j < 2) s_len[j] = 0;
    __syncthreads();
    {
        int cnt0 = 0, cnt1 = 0;
#pragma unroll
        for (int t = j; t < TT; t += 128) {
            cnt0 += (mask[b0 * TT + t] != 0) ? 1 : 0;
            cnt1 += (mask[b1 * TT + t] != 0) ? 1 : 0;
        }
        atomicAdd(&s_len[0], cnt0);
        atomicAdd(&s_len[1], cnt1);
    }
    __syncthreads();
    const int len0 = s_len[0];
    const int len1 = s_len[1];
    const int tmax = (len0 > len1) ? len0 : len1;

    // ---- gold path score (all 128 threads cooperate per batch)
    for (int b = 0; b < 2; b++) {
        const int bb = b0 + b;
        const int lb = (b == 0) ? len0 : len1;
        float gp = 0.0f;
        for (int t = j; t < lb; t += 128) {
            int tg   = tags[bb * TT + t];
            float e  = feat[(bb * TT + t) * LL + tg];
            int prev = (t == 0) ? BOSL : tags[bb * TT + t - 1];
            gp += e + tr[prev * LL + tg];
        }
#pragma unroll
        for (int o = 16; o > 0; o >>= 1) gp += __shfl_down_sync(0xffffffffu, gp, o);
        if (lane == 0) s_red[b][wid] = gp;
    }
    __syncthreads();
    if (j == 0) {
#pragma unroll
        for (int b = 0; b < 2; b++) {
            const int bb = b0 + b;
            const int lb = (b == 0) ? len0 : len1;
            float g = s_red[b][0] + s_red[b][1] + s_red[b][2] + s_red[b][3];
            g += tr[tags[bb * TT + lb - 1] * LL + EOSL];
            s_gold[b] = g;
        }
    }

    // ---- forward recursion init: fv = tr[BOS,:] + feat[:,0,:]
    const float trb = tr[BOSL * LL + j];
    float fv0 = trb + feat[(b0 * TT) * LL + j];
    float fv1 = trb + feat[(b1 * TT) * LL + j];
    if (j == 64) { c_sh[0][0] = fv0; c_sh[0][1] = fv1; }
    __syncthreads();
    float c0 = c_sh[0][0];
    float c1 = c_sh[0][1];

    float ft0 = feat[(b0 * TT + 1) * LL + j];  // len >= 256 always
    float ft1 = feat[(b1 * TT + 1) * LL + j];

    int p = 0;
    for (int t = 1; t < tmax; t++) {
        // phase A: publish u = exp(fv - c) and next normalizer (fv[64])
        float u0 = __expf(fv0 - c0);
        float u1 = __expf(fv1 - c1);
        u_sh[p][0][j] = u0;
        u_sh[p][1][j] = u1;
        if (j == 64) { c_sh[p][0] = fv0; c_sh[p][1] = fv1; }
        __syncthreads();
        float nc0 = c_sh[p][0];
        float nc1 = c_sh[p][1];

        // prefetch next step's emission rows
        float nft0 = ft0, nft1 = ft1;
        if (t + 1 < tmax) {
            nft0 = feat[(b0 * TT + t + 1) * LL + j];
            nft1 = feat[(b1 * TT + t + 1) * LL + j];
        }

        // phase B: v[j] = sum_i u[i] * E[i][j]  (E packed in regs, u via LDS.128 broadcast)
        const ulonglong2* U0 = (const ulonglong2*)(u_sh[p][0]);
        const ulonglong2* U1 = (const ulonglong2*)(u_sh[p][1]);
        ull a0 = 0, a1 = 0, a2 = 0, a3 = 0;   // batch 0 accumulators (packed 0.0f pairs)
        ull d0 = 0, d1 = 0, d2 = 0, d3 = 0;   // batch 1 accumulators
#pragma unroll
        for (int q = 0; q < 16; q++) {
            ulonglong2 xa = U0[2 * q];
            ulonglong2 xb = U0[2 * q + 1];
            ulonglong2 ya = U1[2 * q];
            ulonglong2 yb = U1[2 * q + 1];
            FMA2(a0, xa.x, E2[4 * q],     a0);
            FMA2(d0, ya.x, E2[4 * q],     d0);
            FMA2(a1, xa.y, E2[4 * q + 1], a1);
            FMA2(d1, ya.y, E2[4 * q + 1], d1);
            FMA2(a2, xb.x, E2[4 * q + 2], a2);
            FMA2(d2, yb.x, E2[4 * q + 2], d2);
            FMA2(a3, xb.y, E2[4 * q + 3], a3);
            FMA2(d3, yb.y, E2[4 * q + 3], d3);
        }
        ADD2(a0, a0, a2);
        ADD2(a1, a1, a3);
        ADD2(a0, a0, a1);
        ADD2(d0, d0, d2);
        ADD2(d1, d1, d3);
        ADD2(d0, d0, d1);
        float slo, shi, tlo, thi;
        unpack2(slo, shi, a0);
        unpack2(tlo, thi, d0);
        float s0 = slo + shi;
        float s1 = tlo + thi;

        if (t < len0) fv0 = ft0 + c0 + __logf(s0);
        if (t < len1) fv1 = ft1 + c1 + __logf(s1);
        c0 = nc0; c1 = nc1;
        ft0 = nft0; ft1 = nft1;
        p ^= 1;
    }

    // ---- logZ = logsumexp_j(fv[j] + tr[j][EOS]); result = logZ - gold
    {
        float te = tr[j * LL + EOSL];
        float e0 = __expf((fv0 + te) - c0);
        float e1 = __expf((fv1 + te) - c1);
#pragma unroll
        for (int o = 16; o > 0; o >>= 1) {
            e0 += __shfl_down_sync(0xffffffffu, e0, o);
            e1 += __shfl_down_sync(0xffffffffu, e1, o);
        }
        __syncthreads();
        if (lane == 0) { s_red[0][wid] = e0; s_red[1][wid] = e1; }
        __syncthreads();
        if (j == 0) {
            float z0 = s_red[0][0] + s_red[0][1] + s_red[0][2] + s_red[0][3];
            float z1 = s_red[1][0] + s_red[1][1] + s_red[1][2] + s_red[1][3];
            g_res[b0] = (c0 + __logf(z0)) - s_gold[0];
            g_res[b1] = (c1 + __logf(z1)) - s_gold[1];
        }
    }
}

// deterministic fixed-order mean over the 512 per-batch results
__global__ void crf_reduce(float* __restrict__ out) {
    __shared__ float s[BB];
    int t = threadIdx.x;
    s[t] = g_res[t];
    __syncthreads();
#pragma unroll
    for (int k = BB / 2; k > 0; k >>= 1) {
        if (t < k) s[t] += s[t + k];
        __syncthreads();
    }
    if (t == 0) out[0] = s[0] * (1.0f / (float)BB);
}

extern "C" void kernel_launch(void* const* d_in, const int* in_sizes, int n_in,
                              void* d_out, int out_size) {
    const float* feat = (const float*)d_in[0];
    const int*   tags = (const int*)d_in[1];
    const int*   mask = (const int*)d_in[2];
    const float* tr   = (const float*)d_in[3];

    crf_fwd<<<BB / 2, 128>>>(feat, tags, mask, tr);
    crf_reduce<<<1, BB>>>((float*)d_out);
}